// round 3
// baseline (speedup 1.0000x reference)
#include <cuda_runtime.h>
#include <math_constants.h>

// Problem constants (from reference setup_inputs)
#define N_IMG 2
#define C_CH  256
#define H_F   64
#define W_F   64
#define HW    (H_F * W_F)
#define R_ROI 128
#define PH    7
#define PW    7
#define NBINS (PH * PW)   // 49
#define SCALE 0.0625f

// NHWC scratch: [b][h][w][c], 2*64*64*256 floats = 8 MB
__device__ float TFEAT[N_IMG * HW * C_CH];

// ---------------------------------------------------------------------------
// Transpose NCHW -> NHWC. Per image: A[C=256][HW=4096] -> B[HW][C].
// Classic 32x32 shared-memory tile transpose, coalesced load + store.
// Grid: (HW/32=128, C/32=8, N=2), block (32, 8).
// ---------------------------------------------------------------------------
__global__ void transpose_kernel(const float* __restrict__ feat)
{
    __shared__ float tile[32][33];
    int b   = blockIdx.z;
    int hw0 = blockIdx.x * 32;
    int c0  = blockIdx.y * 32;
    const float* src = feat  + (size_t)b * C_CH * HW;
    float*       dst = TFEAT + (size_t)b * HW * C_CH;
    int tx = threadIdx.x, ty = threadIdx.y;

    #pragma unroll
    for (int i = 0; i < 32; i += 8)
        tile[ty + i][tx] = src[(size_t)(c0 + ty + i) * HW + hw0 + tx];
    __syncthreads();
    #pragma unroll
    for (int i = 0; i < 32; i += 8)
        dst[(size_t)(hw0 + ty + i) * C_CH + c0 + tx] = tile[tx][ty + i];
}

// ---------------------------------------------------------------------------
// Pool kernel. Block = (roi r, channel-half). 256 threads = 8 warps.
// Warp-task = one (ph,pw) bin for 128 channels (lane = 4 channels, float4).
// All lanes share bin bounds -> zero divergence; each inner iteration is a
// single LDG.128 covering 128 consecutive channels (4 cache lines).
// Results staged in shared as [c_local][bin] so the global writeback is a
// contiguous, fully coalesced memcpy into out[r][c][ph][pw].
//
// Bin-boundary arithmetic is VERBATIM from the round-1 kernel that matched
// the reference bit-exactly (reciprocal multiply, NOT a true divide — the
// ceil() at bin edges is ULP-critical).
// ---------------------------------------------------------------------------
__global__ __launch_bounds__(256) void pool_kernel(const float* __restrict__ rois,
                                                   float* __restrict__ out)
{
    __shared__ float sout[128 * NBINS];   // index: c_local*49 + bin

    int r     = blockIdx.x >> 1;
    int chalf = blockIdx.x & 1;
    int tid   = threadIdx.x;
    int warp  = tid >> 5;
    int lane  = tid & 31;

    const float* roi = rois + r * 5;
    int b  = (int)roi[0];
    // jnp.round = round-half-to-even -> rintf
    int sw = (int)rintf(roi[1] * SCALE);
    int sh = (int)rintf(roi[2] * SCALE);
    int ew = (int)rintf(roi[3] * SCALE);
    int eh = (int)rintf(roi[4] * SCALE);

    float roi_w = (float)max(ew - sw + 1, 1);
    float roi_h = (float)max(eh - sh + 1, 1);
    float bin_h = roi_h * (1.0f / PH);   // matches reference bit-exactly (round 1)
    float bin_w = roi_w * (1.0f / PW);

    // float4 view of TFEAT: element (b,h,w,c) -> (b*HW + h*64 + w)*64 + c/4
    const float4* base = (const float4*)TFEAT
                       + (size_t)b * HW * (C_CH / 4)
                       + chalf * 32 + lane;

    for (int bin = warp; bin < NBINS; bin += 8) {
        int ph = bin / PW;
        int pw = bin - ph * PW;

        int hstart = min(max((int)floorf((float)ph * bin_h) + sh, 0), H_F);
        int hend   = min(max((int)ceilf(((float)ph + 1.0f) * bin_h) + sh, 0), H_F);
        int wstart = min(max((int)floorf((float)pw * bin_w) + sw, 0), W_F);
        int wend   = min(max((int)ceilf(((float)pw + 1.0f) * bin_w) + sw, 0), W_F);

        float m0, m1, m2, m3;
        if ((hend <= hstart) || (wend <= wstart)) {
            m0 = m1 = m2 = m3 = 0.0f;
        } else {
            m0 = m1 = m2 = m3 = -CUDART_INF_F;
            for (int h = hstart; h < hend; ++h) {
                const float4* rowp = base + (size_t)(h * W_F) * (C_CH / 4);
                for (int w = wstart; w < wend; ++w) {
                    float4 v = __ldg(rowp + (size_t)w * (C_CH / 4));
                    m0 = fmaxf(m0, v.x);
                    m1 = fmaxf(m1, v.y);
                    m2 = fmaxf(m2, v.z);
                    m3 = fmaxf(m3, v.w);
                }
            }
        }
        int c0 = lane * 4;
        sout[(c0 + 0) * NBINS + bin] = m0;
        sout[(c0 + 1) * NBINS + bin] = m1;
        sout[(c0 + 2) * NBINS + bin] = m2;
        sout[(c0 + 3) * NBINS + bin] = m3;
    }
    __syncthreads();

    // Coalesced writeback: block's output region is contiguous 128*49 floats.
    float* obase = out + (size_t)r * C_CH * NBINS + (size_t)chalf * 128 * NBINS;
    for (int i = tid; i < 128 * NBINS; i += 256)
        obase[i] = sout[i];
}

extern "C" void kernel_launch(void* const* d_in, const int* in_sizes, int n_in,
                              void* d_out, int out_size)
{
    const float* feat = (const float*)d_in[0];
    const float* rois = (const float*)d_in[1];
    float* out = (float*)d_out;

    dim3 tgrid(HW / 32, C_CH / 32, N_IMG);
    dim3 tblock(32, 8);
    transpose_kernel<<<tgrid, tblock>>>(feat);

    pool_kernel<<<R_ROI * 2, 256>>>(rois, out);
}

// round 4
// speedup vs baseline: 2.2299x; 2.2299x over previous
#include <cuda_runtime.h>
#include <math_constants.h>

// Problem constants (from reference setup_inputs)
#define N_IMG 2
#define C_CH  256
#define H_F   64
#define W_F   64
#define HW    (H_F * W_F)
#define R_ROI 128
#define PH    7
#define PW    7
#define NBINS (PH * PW)   // 49
#define SCALE 0.0625f

// NHWC scratch: [b][h][w][c], 8 MB
__device__ float TFEAT[N_IMG * HW * C_CH];
// bin-major output scratch: [r][bin][c], 128*49*256 floats = 6.4 MB
__device__ float OSCR[R_ROI * NBINS * C_CH];

// ---------------------------------------------------------------------------
// Kernel 1: NCHW -> NHWC transpose (measured ~0.6us in round 3).
// ---------------------------------------------------------------------------
__global__ void transpose_kernel(const float* __restrict__ feat)
{
    __shared__ float tile[32][33];
    int b   = blockIdx.z;
    int hw0 = blockIdx.x * 32;
    int c0  = blockIdx.y * 32;
    const float* src = feat  + (size_t)b * C_CH * HW;
    float*       dst = TFEAT + (size_t)b * HW * C_CH;
    int tx = threadIdx.x, ty = threadIdx.y;

    #pragma unroll
    for (int i = 0; i < 32; i += 8)
        tile[ty + i][tx] = src[(size_t)(c0 + ty + i) * HW + hw0 + tx];
    __syncthreads();
    #pragma unroll
    for (int i = 0; i < 32; i += 8)
        dst[(size_t)(hw0 + ty + i) * C_CH + c0 + tx] = tile[tx][ty + i];
}

// ---------------------------------------------------------------------------
// Kernel 2: pool. One warp = one (roi, bin, channel-half).
// 128*49*2 = 12544 warp-tasks = 1568 blocks of 8 warps -> full chip occupancy.
// Lane = 4 consecutive channels (one float4/LDG.128 per pixel per warp).
// Store: 512B contiguous per warp into bin-major OSCR (fully coalesced).
// Bin-bound arithmetic is verbatim from the bit-exact round-1 kernel.
// ---------------------------------------------------------------------------
__global__ __launch_bounds__(256) void pool_kernel(const float* __restrict__ rois)
{
    int wg   = blockIdx.x * 8 + (threadIdx.x >> 5);   // global warp-task id
    int lane = threadIdx.x & 31;
    if (wg >= R_ROI * NBINS * 2) return;

    int half = wg & 1;
    int rem  = wg >> 1;
    int bin  = rem % NBINS;
    int r    = rem / NBINS;
    int ph   = bin / PW;
    int pw   = bin - ph * PW;

    const float* roi = rois + r * 5;
    int b  = (int)roi[0];
    int sw = (int)rintf(roi[1] * SCALE);
    int sh = (int)rintf(roi[2] * SCALE);
    int ew = (int)rintf(roi[3] * SCALE);
    int eh = (int)rintf(roi[4] * SCALE);

    float roi_w = (float)max(ew - sw + 1, 1);
    float roi_h = (float)max(eh - sh + 1, 1);
    float bin_h = roi_h * (1.0f / PH);   // bit-exact vs reference
    float bin_w = roi_w * (1.0f / PW);

    int hstart = min(max((int)floorf((float)ph * bin_h) + sh, 0), H_F);
    int hend   = min(max((int)ceilf(((float)ph + 1.0f) * bin_h) + sh, 0), H_F);
    int wstart = min(max((int)floorf((float)pw * bin_w) + sw, 0), W_F);
    int wend   = min(max((int)ceilf(((float)pw + 1.0f) * bin_w) + sw, 0), W_F);

    float m0, m1, m2, m3;
    if ((hend <= hstart) || (wend <= wstart)) {
        m0 = m1 = m2 = m3 = 0.0f;
    } else {
        m0 = m1 = m2 = m3 = -CUDART_INF_F;
        const float4* base = (const float4*)TFEAT
                           + (size_t)b * HW * (C_CH / 4)
                           + half * 32 + lane;
        for (int h = hstart; h < hend; ++h) {
            const float4* rowp = base + (size_t)(h * W_F) * (C_CH / 4);
            for (int w = wstart; w < wend; ++w) {
                float4 v = __ldg(rowp + (size_t)w * (C_CH / 4));
                m0 = fmaxf(m0, v.x);
                m1 = fmaxf(m1, v.y);
                m2 = fmaxf(m2, v.z);
                m3 = fmaxf(m3, v.w);
            }
        }
    }

    // OSCR[r][bin][half*128 + lane*4 .. +3]  — warp writes 512B contiguous
    float4* op = (float4*)(OSCR + ((size_t)(r * NBINS + bin)) * C_CH + half * 128);
    op[lane] = make_float4(m0, m1, m2, m3);
}

// ---------------------------------------------------------------------------
// Kernel 3: per-(roi, channel-half) transpose  OSCR[r][bin][c] -> out[r][c][bin].
// Block = (r, half), 256 threads. Stage 49x128 floats in padded shared
// (stride 129 -> conflict-free on the strided read), both global sides
// fully coalesced contiguous regions.
// ---------------------------------------------------------------------------
__global__ __launch_bounds__(256) void otrans_kernel(float* __restrict__ out)
{
    __shared__ float sh[NBINS * 129];   // [bin][cl], padded

    int r    = blockIdx.x >> 1;
    int half = blockIdx.x & 1;
    int tid  = threadIdx.x;

    const float* src = OSCR + (size_t)r * NBINS * C_CH + half * 128;

    // load: i = bin*128 + cl ; src offset = bin*256 + cl (contiguous 512B runs)
    for (int i = tid; i < NBINS * 128; i += 256) {
        int bin = i >> 7;
        int cl  = i & 127;
        sh[bin * 129 + cl] = src[bin * C_CH + cl];
    }
    __syncthreads();

    // store: j = cl*49 + bin over contiguous out region out[r][half*128 + cl][bin]
    float* dst = out + (size_t)r * C_CH * NBINS + (size_t)half * 128 * NBINS;
    for (int j = tid; j < 128 * NBINS; j += 256) {
        int cl  = j / NBINS;
        int bin = j - cl * NBINS;
        dst[j] = sh[bin * 129 + cl];
    }
}

extern "C" void kernel_launch(void* const* d_in, const int* in_sizes, int n_in,
                              void* d_out, int out_size)
{
    const float* feat = (const float*)d_in[0];
    const float* rois = (const float*)d_in[1];
    float* out = (float*)d_out;

    dim3 tgrid(HW / 32, C_CH / 32, N_IMG);
    dim3 tblock(32, 8);
    transpose_kernel<<<tgrid, tblock>>>(feat);

    int tasks = R_ROI * NBINS * 2;            // 12544 warps
    pool_kernel<<<(tasks + 7) / 8, 256>>>(rois);

    otrans_kernel<<<R_ROI * 2, 256>>>(out);
}

// round 5
// speedup vs baseline: 2.9394x; 1.3182x over previous
#include <cuda_runtime.h>
#include <math_constants.h>

// Problem constants (from reference setup_inputs)
#define N_IMG 2
#define C_CH  256
#define H_F   64
#define W_F   64
#define HW    (H_F * W_F)
#define R_ROI 128
#define PH    7
#define PW    7
#define NBINS (PH * PW)   // 49
#define SCALE 0.0625f
#define C4    (C_CH / 4)  // 64 float4 per pixel
#define ROWSTRIDE4 (W_F * C4)  // 4096 float4 per feature row

// NHWC scratch: [b][h][w][c], 8 MB
__device__ float TFEAT[N_IMG * HW * C_CH];

// ---------------------------------------------------------------------------
// Kernel 1: NCHW -> NHWC transpose, float4 on both global sides.
// Block (8,32) = 256 threads, 32x32 tile (1 float4 ld + 1 float4 st / thread).
// Shared pad 33 -> both scalar shared phases conflict-free.
// ---------------------------------------------------------------------------
__global__ __launch_bounds__(256) void transpose_kernel(const float* __restrict__ feat)
{
    __shared__ float tile[32][33];   // [c_local][hw_local]
    int b   = blockIdx.z;
    int hw0 = blockIdx.x * 32;
    int c0  = blockIdx.y * 32;
    int tx  = threadIdx.x;   // 0..7
    int ty  = threadIdx.y;   // 0..31

    const float4* src4 = (const float4*)(feat + (size_t)b * C_CH * HW);
    float4*       dst4 = (float4*)(TFEAT + (size_t)b * HW * C_CH);

    // load: c = c0+ty, hw quad = tx  (128B coalesced per 4-lane row group)
    float4 v = src4[(size_t)(c0 + ty) * (HW / 4) + (hw0 / 4) + tx];
    tile[ty][4 * tx + 0] = v.x;
    tile[ty][4 * tx + 1] = v.y;
    tile[ty][4 * tx + 2] = v.z;
    tile[ty][4 * tx + 3] = v.w;
    __syncthreads();

    // store: hw = hw0+ty, c quad = tx
    float4 o;
    o.x = tile[4 * tx + 0][ty];
    o.y = tile[4 * tx + 1][ty];
    o.z = tile[4 * tx + 2][ty];
    o.w = tile[4 * tx + 3][ty];
    dst4[(size_t)(hw0 + ty) * C4 + (c0 / 4) + tx] = o;
}

// ---------------------------------------------------------------------------
// Kernel 2: pool + fused output writeback.
// Block = (r, half, bin-group of 7). 7 warps/block, warp = one bin x 128 ch.
// Inner loop 2x2 unrolled -> 4 independent LDG.128 in flight.
// Results staged in shared [bin7][132], written to out[r][c][g*7..+6] as
// contiguous 28B runs (no OSCR scratch, no extra kernel).
// Bin-bound arithmetic verbatim from the bit-exact kernel.
// ---------------------------------------------------------------------------
__global__ __launch_bounds__(224) void pool_kernel(const float* __restrict__ rois,
                                                   float* __restrict__ out)
{
    __shared__ float sh[PH * 132];   // [bin_local][c_local], pad to 132 (16B aligned rows)

    int blk  = blockIdx.x;           // r*14 + half*7 + g
    int g    = blk % 7;
    int half = (blk / 7) & 1;
    int r    = blk / 14;
    int tid  = threadIdx.x;
    int warp = tid >> 5;             // 0..6 = bin_local
    int lane = tid & 31;
    int bin  = g * 7 + warp;         // 0..48
    int ph   = bin / PW;
    int pw   = bin - ph * PW;

    const float* roi = rois + r * 5;
    int b  = (int)roi[0];
    int sw = (int)rintf(roi[1] * SCALE);
    int sh_ = (int)rintf(roi[2] * SCALE);
    int ew = (int)rintf(roi[3] * SCALE);
    int eh = (int)rintf(roi[4] * SCALE);

    float roi_w = (float)max(ew - sw + 1, 1);
    float roi_h = (float)max(eh - sh_ + 1, 1);
    float bin_h = roi_h * (1.0f / PH);   // bit-exact vs reference
    float bin_w = roi_w * (1.0f / PW);

    int hstart = min(max((int)floorf((float)ph * bin_h) + sh_, 0), H_F);
    int hend   = min(max((int)ceilf(((float)ph + 1.0f) * bin_h) + sh_, 0), H_F);
    int wstart = min(max((int)floorf((float)pw * bin_w) + sw, 0), W_F);
    int wend   = min(max((int)ceilf(((float)pw + 1.0f) * bin_w) + sw, 0), W_F);

    float4 ma, mb;
    if ((hend <= hstart) || (wend <= wstart)) {
        ma = make_float4(0.f, 0.f, 0.f, 0.f);
        mb = ma;
    } else {
        ma = make_float4(-CUDART_INF_F, -CUDART_INF_F, -CUDART_INF_F, -CUDART_INF_F);
        mb = ma;
        const float4* base = (const float4*)TFEAT
                           + (size_t)b * HW * C4 + half * 32 + lane;
        int h = hstart;
        for (; h + 1 < hend; h += 2) {
            const float4* r0 = base + (size_t)h * ROWSTRIDE4;
            const float4* r1 = r0 + ROWSTRIDE4;
            int w = wstart;
            for (; w + 1 < wend; w += 2) {
                float4 a0 = __ldg(r0 + (size_t)w * C4);
                float4 a1 = __ldg(r0 + (size_t)(w + 1) * C4);
                float4 b0 = __ldg(r1 + (size_t)w * C4);
                float4 b1 = __ldg(r1 + (size_t)(w + 1) * C4);
                ma.x = fmaxf(ma.x, fmaxf(a0.x, a1.x));
                ma.y = fmaxf(ma.y, fmaxf(a0.y, a1.y));
                ma.z = fmaxf(ma.z, fmaxf(a0.z, a1.z));
                ma.w = fmaxf(ma.w, fmaxf(a0.w, a1.w));
                mb.x = fmaxf(mb.x, fmaxf(b0.x, b1.x));
                mb.y = fmaxf(mb.y, fmaxf(b0.y, b1.y));
                mb.z = fmaxf(mb.z, fmaxf(b0.z, b1.z));
                mb.w = fmaxf(mb.w, fmaxf(b0.w, b1.w));
            }
            if (w < wend) {
                float4 a0 = __ldg(r0 + (size_t)w * C4);
                float4 b0 = __ldg(r1 + (size_t)w * C4);
                ma.x = fmaxf(ma.x, a0.x); ma.y = fmaxf(ma.y, a0.y);
                ma.z = fmaxf(ma.z, a0.z); ma.w = fmaxf(ma.w, a0.w);
                mb.x = fmaxf(mb.x, b0.x); mb.y = fmaxf(mb.y, b0.y);
                mb.z = fmaxf(mb.z, b0.z); mb.w = fmaxf(mb.w, b0.w);
            }
        }
        if (h < hend) {
            const float4* r0 = base + (size_t)h * ROWSTRIDE4;
            int w = wstart;
            for (; w + 1 < wend; w += 2) {
                float4 a0 = __ldg(r0 + (size_t)w * C4);
                float4 a1 = __ldg(r0 + (size_t)(w + 1) * C4);
                ma.x = fmaxf(ma.x, a0.x); ma.y = fmaxf(ma.y, a0.y);
                ma.z = fmaxf(ma.z, a0.z); ma.w = fmaxf(ma.w, a0.w);
                mb.x = fmaxf(mb.x, a1.x); mb.y = fmaxf(mb.y, a1.y);
                mb.z = fmaxf(mb.z, a1.z); mb.w = fmaxf(mb.w, a1.w);
            }
            if (w < wend) {
                float4 a0 = __ldg(r0 + (size_t)w * C4);
                ma.x = fmaxf(ma.x, a0.x); ma.y = fmaxf(ma.y, a0.y);
                ma.z = fmaxf(ma.z, a0.z); ma.w = fmaxf(ma.w, a0.w);
            }
        }
        ma.x = fmaxf(ma.x, mb.x); ma.y = fmaxf(ma.y, mb.y);
        ma.z = fmaxf(ma.z, mb.z); ma.w = fmaxf(ma.w, mb.w);
    }

    // stage: sh[warp][lane*4 .. +3]  (float4 STS, conflict-free)
    *(float4*)&sh[warp * 132 + lane * 4] = ma;
    __syncthreads();

    // writeback: out[r][half*128 + c][g*7 + binl], 128 runs of 7 contiguous floats
    float* dst = out + (size_t)r * C_CH * NBINS + (size_t)half * 128 * NBINS + g * 7;
    for (int j = tid; j < 128 * 7; j += 224) {
        int c    = j / 7;
        int binl = j - c * 7;
        dst[(size_t)c * NBINS + binl] = sh[binl * 132 + c];
    }
}

extern "C" void kernel_launch(void* const* d_in, const int* in_sizes, int n_in,
                              void* d_out, int out_size)
{
    const float* feat = (const float*)d_in[0];
    const float* rois = (const float*)d_in[1];
    float* out = (float*)d_out;

    dim3 tgrid(HW / 32, C_CH / 32, N_IMG);
    dim3 tblock(8, 32);
    transpose_kernel<<<tgrid, tblock>>>(feat);

    pool_kernel<<<R_ROI * 2 * 7, 224>>>(rois, out);
}